// round 17
// baseline (speedup 1.0000x reference)
#include <cuda_runtime.h>
#include <cuda_fp16.h>
#include <math.h>
#include <stdint.h>

// StableMoEGate v12: fp16 m16n8k16 2-PASS GEMM (x_hi * (W_hi + W_lo)) + exact
// fp32 fixup kernel for near-tie tokens (gap12 or gap23 < 1e-2).
// logits = x @ W^T (T=16384, H=4096, E=64); softmax; top-2; renorm softmax.
// Output: single f32 buffer [2T scores][2T idx-as-float][1 aux=0].

#define Hdim 4096
#define Edim 64
#define MT   64
#define NCHUNK 32
#define SMEM_BYTES 65536
#define TAU  1e-2f

// W pre-split to fp16 hi/lo: [spl][kstep:256][n:64][quad:4][half16:2][bit:2]
__device__ __half g_wsplit[2 * 64 * 4096];
// worklist of ambiguous tokens: {tok, e1..e4, Z, best1, pad}
__device__ float g_wl[16384][8];
__device__ int   g_wlcnt;

static __device__ __forceinline__ uint32_t smem_u32(const void* p) {
    uint32_t a;
    asm("{ .reg .u64 t; cvta.to.shared.u64 t, %1; cvt.u32.u64 %0, t; }" : "=r"(a) : "l"(p));
    return a;
}
static __device__ __forceinline__ uint32_t h2u(__half2 h) {
    return *reinterpret_cast<uint32_t*>(&h);
}

__global__ void __launch_bounds__(256) split_w_kernel(const float* __restrict__ W) {
    if (blockIdx.x == 0 && threadIdx.x == 0) g_wlcnt = 0;   // reset worklist
    const int i = blockIdx.x * 256 + threadIdx.x;
    if (i < 64 * 4096) {
        const int n = i >> 12, k = i & 4095;
        const float w = W[(size_t)n * 4096 + k];
        const __half hi = __float2half_rn(w);
        const __half lo = __float2half_rn(w - __half2float(hi));
        const int kin = k & 15;
        const int half = kin >> 3, quad = (kin & 7) >> 1, bit = kin & 1;
        const int idx = ((k >> 4) * 64 + n) * 16 + quad * 4 + half * 2 + bit;
        g_wsplit[idx]          = hi;
        g_wsplit[262144 + idx] = lo;
    }
}

#define MMAH(d, a0, a1, a2, a3, b0, b1)                                          \
    asm("mma.sync.aligned.m16n8k16.row.col.f32.f16.f16.f32 "                     \
        "{%0,%1,%2,%3}, {%4,%5,%6,%7}, {%8,%9}, {%0,%1,%2,%3};"                  \
        : "+f"(d[0]), "+f"(d[1]), "+f"(d[2]), "+f"(d[3])                         \
        : "r"(a0), "r"(a1), "r"(a2), "r"(a3), "r"(b0), "r"(b1))

__global__ void __launch_bounds__(256, 2) moe_gate_v12_kernel(
    const float* __restrict__ x,
    float* __restrict__ out,
    int T)
{
    extern __shared__ float smem[];
    const uint32_t sbase = smem_u32(smem);

    const int tid  = threadIdx.x;
    const int lid  = tid & 31;
    const int wid  = tid >> 5;
    const int g    = wid >> 1;            // K-group 0..3 : k in [g*1024, +1024)
    const int tokg = wid & 1;             // token half
    const int gid  = lid >> 2;            // 0..7
    const int tid4 = lid & 3;             // 0..3
    const int m0   = blockIdx.x * MT;

    // ---- cp.async B: 8 x 16B per thread per chunk ----
    uint32_t woff[8];
    #pragma unroll
    for (int j = 0; j < 8; j++) {
        const int id     = j * 256 + tid;
        const int half16 = id & 1;
        const int n      = (id >> 1) & 63;
        const int spl    = (id >> 7) & 1;
        const int s      = (id >> 8) & 1;
        const int gg     = (id >> 9) & 3;
        woff[j] = (uint32_t)((spl * 262144 + ((gg * 64 + s) * 64 + n) * 16 + half16 * 8) * 2);
    }
    const char* wbase = (const char*)g_wsplit;

    // ---- A float2 byte offsets (chunk 0, step 0) ----
    uint32_t aoff[8];
    #pragma unroll
    for (int m = 0; m < 2; m++) {
        const int r = m0 + tokg * 32 + m * 16 + gid;
        const int c = g * 1024 + tid4 * 2;
        aoff[m * 4 + 0] = (uint32_t)(((size_t)r * Hdim + c) * 4);
        aoff[m * 4 + 1] = (uint32_t)(((size_t)(r + 8) * Hdim + c) * 4);
        aoff[m * 4 + 2] = (uint32_t)(((size_t)r * Hdim + c + 8) * 4);
        aoff[m * 4 + 3] = (uint32_t)(((size_t)(r + 8) * Hdim + c + 8) * 4);
    }
    const char* xb = (const char*)x;

    float acc0[8][4], acc1[8][4];
    #pragma unroll
    for (int nt = 0; nt < 8; nt++)
        #pragma unroll
        for (int q = 0; q < 4; q++) { acc0[nt][q] = 0.0f; acc1[nt][q] = 0.0f; }

    auto issueB = [&](int c) {
        const uint32_t dbase = sbase + (uint32_t)(c & 1) * 32768u + (uint32_t)tid * 16u;
        #pragma unroll
        for (int j = 0; j < 8; j++)
            asm volatile("cp.async.cg.shared.global [%0], [%1], 16;"
                         :: "r"(dbase + (uint32_t)(j * 4096)),
                            "l"(wbase + woff[j] + (uint32_t)c * 4096u));
        asm volatile("cp.async.commit_group;" ::: "memory");
    };

    issueB(0);

    for (int c = 0; c < NCHUNK; c++) {
        asm volatile("cp.async.wait_group 0;" ::: "memory");
        __syncthreads();
        if (c + 1 < NCHUNK) issueB(c + 1);

        #pragma unroll
        for (int s = 0; s < 2; s++) {
            const uint32_t ka = (uint32_t)((c * 32 + s * 16) * 4);
            uint32_t ahi[8];
            #pragma unroll
            for (int i = 0; i < 8; i++) {
                const float2 v = *(const float2*)(xb + aoff[i] + ka);
                ahi[i] = h2u(__float22half2_rn(v));
            }

            const uint32_t b0a = sbase + (uint32_t)((c & 1) * 32768)
                               + (uint32_t)(((g * 2 + s) * 2) * 2048)
                               + (uint32_t)(gid * 32 + tid4 * 8);
            #pragma unroll
            for (int nt = 0; nt < 8; nt++) {
                uint32_t bh0, bh1, bl0, bl1;
                asm volatile("ld.shared.v2.b32 {%0,%1},[%2];"
                             : "=r"(bh0), "=r"(bh1) : "r"(b0a + (uint32_t)(nt * 256)));
                asm volatile("ld.shared.v2.b32 {%0,%1},[%2];"
                             : "=r"(bl0), "=r"(bl1) : "r"(b0a + (uint32_t)(nt * 256) + 2048u));
                MMAH(acc0[nt], ahi[0], ahi[1], ahi[2], ahi[3], bh0, bh1);
                MMAH(acc1[nt], ahi[4], ahi[5], ahi[6], ahi[7], bh0, bh1);
                MMAH(acc0[nt], ahi[0], ahi[1], ahi[2], ahi[3], bl0, bl1);
                MMAH(acc1[nt], ahi[4], ahi[5], ahi[6], ahi[7], bl0, bl1);
            }
        }
    }
    __syncthreads();

    // ---- split-K(4) reduction into logits smem [64][68] ----
    #pragma unroll
    for (int gg = 0; gg < 4; gg++) {
        if (g == gg) {
            #pragma unroll
            for (int m = 0; m < 2; m++) {
                const int r = tokg * 32 + m * 16 + gid;
                #pragma unroll
                for (int nt = 0; nt < 8; nt++) {
                    const float* a4 = (m == 0) ? acc0[nt] : acc1[nt];
                    const int col = nt * 8 + tid4 * 2;
                    if (gg == 0) {
                        smem[r * 68 + col]           = a4[0];
                        smem[r * 68 + col + 1]       = a4[1];
                        smem[(r + 8) * 68 + col]     = a4[2];
                        smem[(r + 8) * 68 + col + 1] = a4[3];
                    } else {
                        smem[r * 68 + col]           += a4[0];
                        smem[r * 68 + col + 1]       += a4[1];
                        smem[(r + 8) * 68 + col]     += a4[2];
                        smem[(r + 8) * 68 + col + 1] += a4[3];
                    }
                }
            }
        }
        __syncthreads();
    }

    if (tid < MT) {
        const float* row = smem + tid * 68;
        float b1 = -3.4e38f, b2 = -3.4e38f, b3 = -3.4e38f, b4 = -3.4e38f;
        int i1 = 0, i2 = 0, i3 = 0, i4 = 0;
        #pragma unroll 8
        for (int e = 0; e < Edim; e++) {
            const float l = row[e];
            if (l > b1)      { b4=b3;i4=i3; b3=b2;i3=i2; b2=b1;i2=i1; b1=l;i1=e; }
            else if (l > b2) { b4=b3;i4=i3; b3=b2;i3=i2; b2=l;i2=e; }
            else if (l > b3) { b4=b3;i4=i3; b3=l;i3=e; }
            else if (l > b4) { b4=l;i4=e; }
        }
        float Z = 0.0f;
        #pragma unroll 8
        for (int e = 0; e < Edim; e++) Z += expf(row[e] - b1);

        const int m = m0 + tid;
        if ((b1 - b2 < TAU) || (b2 - b3 < TAU)) {
            const int slot = atomicAdd(&g_wlcnt, 1);
            g_wl[slot][0] = (float)m;
            g_wl[slot][1] = (float)i1;
            g_wl[slot][2] = (float)i2;
            g_wl[slot][3] = (float)i3;
            g_wl[slot][4] = (float)i4;
            g_wl[slot][5] = Z;
            g_wl[slot][6] = b1;
        } else {
            const float s1 = 1.0f / Z;
            const float s2 = expf(b2 - b1) / Z;
            const float p1 = 1.0f / (1.0f + expf(s2 - s1));
            out[2 * m + 0] = p1;
            out[2 * m + 1] = 1.0f - p1;
            float* oi = out + 2 * T;
            oi[2 * m + 0] = (float)i1;
            oi[2 * m + 1] = (float)i2;
        }
    }
    if (blockIdx.x == 0 && tid == 0) out[4 * T] = 0.0f;
}

// Exact fp32 refinement of worklist tokens: recompute 4 candidate logits.
__global__ void __launch_bounds__(256) fixup_kernel(
    const float* __restrict__ x,
    const float* __restrict__ W,
    float* __restrict__ out,
    int T)
{
    const int gw   = (blockIdx.x * 256 + threadIdx.x) >> 5;
    const int lane = threadIdx.x & 31;
    const int nw   = (gridDim.x * 256) >> 5;
    const int nrec = g_wlcnt;

    for (int r = gw; r < nrec; r += nw) {
        const float* rec = g_wl[r];
        const int tok = (int)rec[0];
        int e[4] = {(int)rec[1], (int)rec[2], (int)rec[3], (int)rec[4]};
        const float Z = rec[5], bref = rec[6];

        // sort candidates ascending by expert index (stable top-k tie rule)
        #pragma unroll
        for (int a = 0; a < 3; a++)
            #pragma unroll
            for (int b = 0; b < 3 - a; b++)
                if (e[b] > e[b + 1]) { int t = e[b]; e[b] = e[b + 1]; e[b + 1] = t; }

        const float4* xr = (const float4*)(x + (size_t)tok * Hdim);
        const float4* w0 = (const float4*)(W + (size_t)e[0] * Hdim);
        const float4* w1 = (const float4*)(W + (size_t)e[1] * Hdim);
        const float4* w2 = (const float4*)(W + (size_t)e[2] * Hdim);
        const float4* w3 = (const float4*)(W + (size_t)e[3] * Hdim);

        float d0 = 0, d1 = 0, d2 = 0, d3 = 0;
        for (int i = lane; i < Hdim / 4; i += 32) {
            const float4 xv = xr[i];
            float4 wv;
            wv = w0[i]; d0 += xv.x*wv.x + xv.y*wv.y + xv.z*wv.z + xv.w*wv.w;
            wv = w1[i]; d1 += xv.x*wv.x + xv.y*wv.y + xv.z*wv.z + xv.w*wv.w;
            wv = w2[i]; d2 += xv.x*wv.x + xv.y*wv.y + xv.z*wv.z + xv.w*wv.w;
            wv = w3[i]; d3 += xv.x*wv.x + xv.y*wv.y + xv.z*wv.z + xv.w*wv.w;
        }
        #pragma unroll
        for (int off = 16; off; off >>= 1) {
            d0 += __shfl_xor_sync(0xFFFFFFFFu, d0, off);
            d1 += __shfl_xor_sync(0xFFFFFFFFu, d1, off);
            d2 += __shfl_xor_sync(0xFFFFFFFFu, d2, off);
            d3 += __shfl_xor_sync(0xFFFFFFFFu, d3, off);
        }

        if (lane == 0) {
            const float dv[4] = {d0, d1, d2, d3};
            float v1 = -3.4e38f, v2 = -3.4e38f;
            int j1 = 0, j2 = 0;
            #pragma unroll
            for (int j = 0; j < 4; j++) {
                const float v = dv[j];
                if (v > v1)      { v2 = v1; j2 = j1; v1 = v; j1 = e[j]; }
                else if (v > v2) { v2 = v; j2 = e[j]; }
            }
            const float s1 = expf(v1 - bref) / Z;
            const float s2 = expf(v2 - bref) / Z;
            const float p1 = 1.0f / (1.0f + expf(s2 - s1));
            out[2 * tok + 0] = p1;
            out[2 * tok + 1] = 1.0f - p1;
            float* oi = out + 2 * T;
            oi[2 * tok + 0] = (float)j1;
            oi[2 * tok + 1] = (float)j2;
        }
    }
}

extern "C" void kernel_launch(void* const* d_in, const int* in_sizes, int n_in,
                              void* d_out, int out_size)
{
    const float* x = (const float*)d_in[0];
    const float* W = (const float*)d_in[1];
    int T = in_sizes[0] / Hdim;   // 16384
    (void)n_in; (void)out_size;

    static bool attr_done = false;
    if (!attr_done) {
        cudaFuncSetAttribute(moe_gate_v12_kernel,
                             cudaFuncAttributeMaxDynamicSharedMemorySize, SMEM_BYTES);
        attr_done = true;
    }
    split_w_kernel<<<1024, 256>>>(W);
    moe_gate_v12_kernel<<<T / MT, 256, SMEM_BYTES>>>(x, (float*)d_out, T);
    fixup_kernel<<<128, 256>>>(x, W, (float*)d_out, T);
}